// round 15
// baseline (speedup 1.0000x reference)
#include <cuda_runtime.h>
#include <cuda_fp16.h>
#include <cstdint>
#include <math.h>

#define N_NODES 100000
#define N_FEAT  100
#define HID     32
#define N_EDGES 1600000
#define ELL_CAP 128         // max in-degree slot (Poisson(16): P(>128) ~ 0)

// ---- k1 MMA tile config ----
#define MROWS   128         // nodes per CTA
#define KTILES  13          // 13 * 8 = 104 >= 100
#define KPAD2   (KTILES*8)
#define XS      108         // sX row stride (floats): 12r%32 pattern, conflict-free
#define WS      33          // sW row stride (floats)
#define STG_S   36          // staging row stride (floats)
#define SM_WHI  (MROWS*XS)                 // float offset of Whi
#define SM_WLO  (SM_WHI + KPAD2*WS)
#define SMEM_K1 ((SM_WLO + KPAD2*WS) * 4)  // bytes = 82,752

// Scratch (static device globals — no allocations allowed)
__device__ float g_xnf[N_NODES * HID];                        // fp32 normalized feats
__device__ __align__(16) unsigned g_xnh[(N_NODES + 1) * 16];  // half2-packed rows (64B)
__device__ float g_nrm[N_NODES + 1];                          // row norms
__device__ int   g_cnt[N_NODES];                              // in-degree counters
__device__ int   g_col[N_NODES * ELL_CAP];                    // ELL source lists

// ---------------------------------------------------------------------------
// K0: zero degree counters (side stream, parallel with k1)
// ---------------------------------------------------------------------------
__global__ void k_zero() {
    int i = blockIdx.x * blockDim.x + threadIdx.x;
    if (i * 4 < N_NODES) *(int4*)&g_cnt[i * 4] = make_int4(0, 0, 0, 0);
}

// ---------------------------------------------------------------------------
// K1 via tensor cores: x = relu(X @ W1^T + b1); xn = x/||x||.
// mma.sync m16n8k8 tf32 (sm_80+ → legal on plain sm_103), 3xTF32 split for
// fp32-grade accuracy. 8 warps x 16 rows. Coalesced smem-staged epilogue.
// ---------------------------------------------------------------------------
#define MMA_TF32(c0,c1,c2,c3,a0,a1,a2,a3,b0,b1) \
    asm volatile("mma.sync.aligned.m16n8k8.row.col.f32.tf32.tf32.f32 " \
        "{%0,%1,%2,%3}, {%4,%5,%6,%7}, {%8,%9}, {%0,%1,%2,%3};" \
        : "+f"(c0), "+f"(c1), "+f"(c2), "+f"(c3) \
        : "r"(a0), "r"(a1), "r"(a2), "r"(a3), "r"(b0), "r"(b1))

__device__ __forceinline__ uint32_t tf32_hi(float x) {
    uint32_t h;
    asm("cvt.rna.tf32.f32 %0, %1;" : "=r"(h) : "f"(x));
    return h;
}

__global__ void __launch_bounds__(256) k1_mma(
    const float* __restrict__ X,
    const float* __restrict__ W1,
    const float* __restrict__ b1)
{
    extern __shared__ float smem[];
    float* sX   = smem;               // [128][108] fp32
    float* sWhi = smem + SM_WHI;      // [104][33]  tf32-hi (as f32 bits)
    float* sWlo = smem + SM_WLO;      // [104][33]  residual

    const int tid   = threadIdx.x;
    const int node0 = blockIdx.x * MROWS;

    // W1 [32][100] -> transposed hi/lo [k][n], zero-padded k 100..103
    for (int i = tid; i < KPAD2 * HID; i += 256) {
        int k = i >> 5, n = i & 31;
        float w = (k < N_FEAT) ? W1[n * N_FEAT + k] : 0.f;
        uint32_t hb = tf32_hi(w);
        float hf = __uint_as_float(hb);
        sWhi[k * WS + n] = hf;
        sWlo[k * WS + n] = w - hf;
    }
    // X tile fp32 (26 float4 per row: 25 data + 1 zero pad for cols 100..103)
    const float4* X4 = (const float4*)X;
    float4* sX4 = (float4*)sX;                 // row stride 27 float4
    for (int i = tid; i < MROWS * 26; i += 256) {
        int r = i / 26, c = i % 26;
        float4 v = make_float4(0.f, 0.f, 0.f, 0.f);
        if (c < 25 && node0 + r < N_NODES) v = X4[(size_t)(node0 + r) * 25 + c];
        sX4[r * 27 + c] = v;
    }
    __syncthreads();

    const int warp = tid >> 5, lane = tid & 31;
    const int g = lane >> 2, t = lane & 3;
    const int row0 = warp * 16 + g;            // second row = row0 + 8

    float c0[4], c1[4], c2[4], c3[4];
    #pragma unroll
    for (int n = 0; n < 4; n++) { c0[n] = c1[n] = c2[n] = c3[n] = 0.f; }

    for (int k = 0; k < KTILES; k++) {
        const int k0 = k * 8;
        // A fragments (m16k8, row-major): hi + lo
        float x0 = sX[ row0      * XS + k0 + t    ];
        float x1 = sX[(row0 + 8) * XS + k0 + t    ];
        float x2 = sX[ row0      * XS + k0 + t + 4];
        float x3 = sX[(row0 + 8) * XS + k0 + t + 4];
        uint32_t ah0 = tf32_hi(x0), ah1 = tf32_hi(x1);
        uint32_t ah2 = tf32_hi(x2), ah3 = tf32_hi(x3);
        uint32_t al0 = __float_as_uint(x0 - __uint_as_float(ah0));
        uint32_t al1 = __float_as_uint(x1 - __uint_as_float(ah1));
        uint32_t al2 = __float_as_uint(x2 - __uint_as_float(ah2));
        uint32_t al3 = __float_as_uint(x3 - __uint_as_float(ah3));

        #pragma unroll
        for (int n = 0; n < 4; n++) {
            const int nb = n * 8 + g;
            uint32_t bh0 = __float_as_uint(sWhi[(k0 + t)     * WS + nb]);
            uint32_t bh1 = __float_as_uint(sWhi[(k0 + t + 4) * WS + nb]);
            uint32_t bl0 = __float_as_uint(sWlo[(k0 + t)     * WS + nb]);
            uint32_t bl1 = __float_as_uint(sWlo[(k0 + t + 4) * WS + nb]);
            MMA_TF32(c0[n], c1[n], c2[n], c3[n], ah0, ah1, ah2, ah3, bh0, bh1);
            MMA_TF32(c0[n], c1[n], c2[n], c3[n], al0, al1, al2, al3, bh0, bh1);
            MMA_TF32(c0[n], c1[n], c2[n], c3[n], ah0, ah1, ah2, ah3, bl0, bl1);
        }
    }

    // epilogue: bias + relu + row norms (rows row0 and row0+8)
    float v0[4][2], v1[4][2];
    float ss0 = 0.f, ss1 = 0.f;
    #pragma unroll
    for (int n = 0; n < 4; n++) {
        const float ba = b1[n * 8 + 2 * t];
        const float bb = b1[n * 8 + 2 * t + 1];
        float a = fmaxf(c0[n] + ba, 0.f);
        float b = fmaxf(c1[n] + bb, 0.f);
        float c = fmaxf(c2[n] + ba, 0.f);
        float d = fmaxf(c3[n] + bb, 0.f);
        v0[n][0] = a; v0[n][1] = b; v1[n][0] = c; v1[n][1] = d;
        ss0 += a * a + b * b;
        ss1 += c * c + d * d;
    }
    ss0 += __shfl_xor_sync(0xffffffffu, ss0, 1);
    ss0 += __shfl_xor_sync(0xffffffffu, ss0, 2);
    ss1 += __shfl_xor_sync(0xffffffffu, ss1, 1);
    ss1 += __shfl_xor_sync(0xffffffffu, ss1, 2);
    const float nrm0 = fmaxf(sqrtf(ss0), 1e-12f), inv0 = 1.f / nrm0;
    const float nrm1 = fmaxf(sqrtf(ss1), 1e-12f), inv1 = 1.f / nrm1;

    __syncthreads();                   // done with sX: reuse as staging
    float* stg = sX;                   // [128][STG_S]
    #pragma unroll
    for (int n = 0; n < 4; n++) {
        *(float2*)&stg[ row0      * STG_S + n * 8 + 2 * t] =
            make_float2(v0[n][0] * inv0, v0[n][1] * inv0);
        *(float2*)&stg[(row0 + 8) * STG_S + n * 8 + 2 * t] =
            make_float2(v1[n][0] * inv1, v1[n][1] * inv1);
    }
    if (t == 0) {
        if (node0 + row0 < N_NODES)     g_nrm[node0 + row0]     = nrm0;
        if (node0 + row0 + 8 < N_NODES) g_nrm[node0 + row0 + 8] = nrm1;
    }
    __syncthreads();

    // coalesced writes: thread -> (row, half-row of 16 floats)
    {
        const int r = tid >> 1, half = tid & 1;
        const int node = node0 + r;
        if (node < N_NODES) {
            const float* src = &stg[r * STG_S + half * 16];
            float4 f0 = *(const float4*)&src[0];
            float4 f1 = *(const float4*)&src[4];
            float4 f2 = *(const float4*)&src[8];
            float4 f3 = *(const float4*)&src[12];
            float4* dst = (float4*)&g_xnf[node * HID + half * 16];
            dst[0] = f0; dst[1] = f1; dst[2] = f2; dst[3] = f3;

            __half2 h0 = __floats2half2_rn(f0.x, f0.y), h1 = __floats2half2_rn(f0.z, f0.w);
            __half2 h2 = __floats2half2_rn(f1.x, f1.y), h3 = __floats2half2_rn(f1.z, f1.w);
            __half2 h4 = __floats2half2_rn(f2.x, f2.y), h5 = __floats2half2_rn(f2.z, f2.w);
            __half2 h6 = __floats2half2_rn(f3.x, f3.y), h7 = __floats2half2_rn(f3.z, f3.w);
            uint4* hd = (uint4*)&g_xnh[node * 16 + half * 8];
            hd[0] = make_uint4(*(unsigned*)&h0, *(unsigned*)&h1,
                               *(unsigned*)&h2, *(unsigned*)&h3);
            hd[1] = make_uint4(*(unsigned*)&h4, *(unsigned*)&h5,
                               *(unsigned*)&h6, *(unsigned*)&h7);
        }
    }
}

// ---------------------------------------------------------------------------
// ELL build: 4 edges per thread, int4 reads, 4 independent atomic chains.
// ---------------------------------------------------------------------------
__global__ void k_ell(const int* __restrict__ esrc,
                      const int* __restrict__ etgt) {
    int e0 = (blockIdx.x * blockDim.x + threadIdx.x) * 4;
    if (e0 >= N_EDGES) return;
    int4 s = *(const int4*)&esrc[e0];
    int4 t = *(const int4*)&etgt[e0];
    int p0 = atomicAdd(&g_cnt[t.x], 1);
    int p1 = atomicAdd(&g_cnt[t.y], 1);
    int p2 = atomicAdd(&g_cnt[t.z], 1);
    int p3 = atomicAdd(&g_cnt[t.w], 1);
    if (p0 < ELL_CAP) g_col[t.x * ELL_CAP + p0] = s.x;
    if (p1 < ELL_CAP) g_col[t.y * ELL_CAP + p1] = s.y;
    if (p2 < ELL_CAP) g_col[t.z * ELL_CAP + p2] = s.z;
    if (p3 < ELL_CAP) g_col[t.w * ELL_CAP + p3] = s.w;
}

// ---------------------------------------------------------------------------
// K_AGG: 8-lane group owns one node (4 nodes/warp); fp16 gathers; 4-way MLP.
// (R12-proven version.)
// ---------------------------------------------------------------------------
__device__ __forceinline__ void edge4(
    int cb, int jj, int deg, int cidx, unsigned gmask, int n, int sub,
    const float4 xt, float beta, float4& acc, float& den)
{
    const bool v0 = (cb + jj     < deg);
    const bool v1 = (cb + jj + 1 < deg);
    const bool v2 = (cb + jj + 2 < deg);
    const bool v3 = (cb + jj + 3 < deg);
    int s0 = __shfl_sync(gmask, cidx, jj,     8);
    int s1 = __shfl_sync(gmask, cidx, jj + 1, 8);
    int s2 = __shfl_sync(gmask, cidx, jj + 2, 8);
    int s3 = __shfl_sync(gmask, cidx, jj + 3, 8);
    s0 = v0 ? s0 : n;  s1 = v1 ? s1 : n;
    s2 = v2 ? s2 : n;  s3 = v3 ? s3 : n;

    const uint2 u0 = *(const uint2*)&g_xnh[s0 * 16 + sub * 2];
    const uint2 u1 = *(const uint2*)&g_xnh[s1 * 16 + sub * 2];
    const uint2 u2 = *(const uint2*)&g_xnh[s2 * 16 + sub * 2];
    const uint2 u3 = *(const uint2*)&g_xnh[s3 * 16 + sub * 2];
    const float r0 = g_nrm[s0], r1 = g_nrm[s1];
    const float r2 = g_nrm[s2], r3 = g_nrm[s3];

    float2 a0 = __half22float2(*(const __half2*)&u0.x);
    float2 b0 = __half22float2(*(const __half2*)&u0.y);
    float2 a1 = __half22float2(*(const __half2*)&u1.x);
    float2 b1 = __half22float2(*(const __half2*)&u1.y);
    float2 a2 = __half22float2(*(const __half2*)&u2.x);
    float2 b2 = __half22float2(*(const __half2*)&u2.y);
    float2 a3 = __half22float2(*(const __half2*)&u3.x);
    float2 b3 = __half22float2(*(const __half2*)&u3.y);

    float d0 = a0.x*xt.x + a0.y*xt.y + b0.x*xt.z + b0.y*xt.w;
    float d1 = a1.x*xt.x + a1.y*xt.y + b1.x*xt.z + b1.y*xt.w;
    float d2 = a2.x*xt.x + a2.y*xt.y + b2.x*xt.z + b2.y*xt.w;
    float d3 = a3.x*xt.x + a3.y*xt.y + b3.x*xt.z + b3.y*xt.w;
    #pragma unroll
    for (int o = 4; o > 0; o >>= 1) {
        d0 += __shfl_xor_sync(gmask, d0, o);
        d1 += __shfl_xor_sync(gmask, d1, o);
        d2 += __shfl_xor_sync(gmask, d2, o);
        d3 += __shfl_xor_sync(gmask, d3, o);
    }
    const float w0 = v0 ? __expf(beta * d0) : 0.0f;
    const float w1 = v1 ? __expf(beta * d1) : 0.0f;
    const float w2 = v2 ? __expf(beta * d2) : 0.0f;
    const float w3 = v3 ? __expf(beta * d3) : 0.0f;
    const float c0 = w0 * r0, c1 = w1 * r1, c2 = w2 * r2, c3 = w3 * r3;
    acc.x = fmaf(c0, a0.x, fmaf(c1, a1.x, fmaf(c2, a2.x, fmaf(c3, a3.x, acc.x))));
    acc.y = fmaf(c0, a0.y, fmaf(c1, a1.y, fmaf(c2, a2.y, fmaf(c3, a3.y, acc.y))));
    acc.z = fmaf(c0, b0.x, fmaf(c1, b1.x, fmaf(c2, b2.x, fmaf(c3, b3.x, acc.z))));
    acc.w = fmaf(c0, b0.y, fmaf(c1, b1.y, fmaf(c2, b2.y, fmaf(c3, b3.y, acc.w))));
    den += (w0 + w1) + (w2 + w3);
}

__global__ void __launch_bounds__(256) k_agg(
    const float* __restrict__ W2,
    const float* __restrict__ b2,
    const float* __restrict__ beta_p,
    float* __restrict__ out)
{
    const int tid  = threadIdx.x;
    const int lane = tid & 31;
    const int g    = lane >> 3;
    const int sub  = lane & 7;
    const unsigned gmask = 0xFFu << (g * 8);
    const int n = blockIdx.x * 32 + (tid >> 5) * 4 + g;   // 100000 = 3125*32

    const float beta = *beta_p;
    const float4 xt = *(const float4*)&g_xnf[n * HID + sub * 4];
    const float nrm_n = g_nrm[n];
    int deg = g_cnt[n];
    if (deg > ELL_CAP) deg = ELL_CAP;
    const int* __restrict__ cols = &g_col[n * ELL_CAP];

    float d = xt.x*xt.x + xt.y*xt.y + xt.z*xt.z + xt.w*xt.w;
    #pragma unroll
    for (int o = 4; o > 0; o >>= 1) d += __shfl_xor_sync(gmask, d, o);
    float wl = __expf(beta * d);
    float cl = wl * nrm_n;
    float4 acc = make_float4(cl * xt.x, cl * xt.y, cl * xt.z, cl * xt.w);
    float  den = wl;

    for (int cb = 0; cb < deg; cb += 8) {
        const int cidx = cols[cb + sub];
        edge4(cb, 0, deg, cidx, gmask, n, sub, xt, beta, acc, den);
        edge4(cb, 4, deg, cidx, gmask, n, sub, xt, beta, acc, den);
    }

    const float inv = 1.0f / den;
    const float4 o4 = make_float4(acc.x * inv, acc.y * inv, acc.z * inv, acc.w * inv);

    const float4 w2a = *(const float4*)&W2[sub * 4];
    const float4 w2b = *(const float4*)&W2[HID + sub * 4];
    float p0 = o4.x * w2a.x + o4.y * w2a.y + o4.z * w2a.z + o4.w * w2a.w;
    float p1 = o4.x * w2b.x + o4.y * w2b.y + o4.z * w2b.z + o4.w * w2b.w;
    #pragma unroll
    for (int o = 4; o > 0; o >>= 1) {
        p0 += __shfl_xor_sync(gmask, p0, o);
        p1 += __shfl_xor_sync(gmask, p1, o);
    }

    if (sub == 0) {
        float l0 = p0 + b2[0];
        float l1 = p1 + b2[1];
        float m  = fmaxf(l0, l1);
        float z  = m + logf(expf(l0 - m) + expf(l1 - m));
        *(float2*)&out[n * 2] = make_float2(l0 - z, l1 - z);
    }
}

// ---------------------------------------------------------------------------
// Launch: {k_zero -> k_ell} on side stream overlaps k1_mma on main stream.
// Inputs (metadata order):
//   0: X [N,100] f32   1: lin1_w [32,100] f32   2: lin1_b [32] f32
//   3: beta scalar f32 4: lin2_w [2,32]  f32   5: lin2_b [2] f32
//   6: edge_index [2,E] i32 (row 0 = src, row 1 = tgt)
// Output: [N,2] f32 log-probs
// ---------------------------------------------------------------------------
extern "C" void kernel_launch(void* const* d_in, const int* in_sizes, int n_in,
                              void* d_out, int out_size)
{
    const float* X    = (const float*)d_in[0];
    const float* W1   = (const float*)d_in[1];
    const float* b1   = (const float*)d_in[2];
    const float* beta = (const float*)d_in[3];
    const float* W2   = (const float*)d_in[4];
    const float* b2   = (const float*)d_in[5];
    const int*   ei   = (const int*)  d_in[6];
    const int* esrc = ei;
    const int* etgt = ei + N_EDGES;
    float* out = (float*)d_out;

    cudaFuncSetAttribute(k1_mma, cudaFuncAttributeMaxDynamicSharedMemorySize,
                         SMEM_K1);

    cudaStream_t s2;
    cudaStreamCreateWithFlags(&s2, cudaStreamNonBlocking);
    cudaEvent_t eFork, eJoin;
    cudaEventCreateWithFlags(&eFork, cudaEventDisableTiming);
    cudaEventCreateWithFlags(&eJoin, cudaEventDisableTiming);

    cudaEventRecord(eFork, 0);
    cudaStreamWaitEvent(s2, eFork, 0);

    // edge pipeline on s2 (independent of k1)
    k_zero<<<(N_NODES / 4 + 255) / 256, 256, 0, s2>>>();
    k_ell<<<(N_EDGES / 4 + 255) / 256, 256, 0, s2>>>(esrc, etgt);

    // node pipeline on main stream (tensor-core lin1)
    const int g1 = (N_NODES + MROWS - 1) / MROWS;   // 782
    k1_mma<<<g1, 256, SMEM_K1>>>(X, W1, b1);

    cudaEventRecord(eJoin, s2);
    cudaStreamWaitEvent(0, eJoin, 0);

    k_agg<<<N_NODES / 32, 256>>>(W2, b2, beta, out);

    cudaEventDestroy(eFork);
    cudaEventDestroy(eJoin);
    cudaStreamDestroy(s2);
}

// round 16
// speedup vs baseline: 1.0620x; 1.0620x over previous
#include <cuda_runtime.h>
#include <cuda_fp16.h>
#include <cstdint>
#include <math.h>

#define N_NODES 100000
#define N_FEAT  100
#define HID     32
#define N_EDGES 1600000
#define NCHUNK  25          // N_FEAT/4 float4 chunks per W1 row
#define ELL_CAP 128         // max in-degree slot (Poisson(16): P(>128) ~ 0)
#define NB      16          // nodes per block in K1

// Scratch (static device globals — no allocations allowed)
__device__ float g_xnf[N_NODES * HID];                        // fp32 normalized feats
__device__ __align__(16) unsigned g_xnh[N_NODES * 16];        // half2-packed rows (64B)
__device__ float g_nrm[N_NODES];                              // row norms
__device__ int   g_cnt[N_NODES];                              // in-degree counters
__device__ int   g_col[N_NODES * ELL_CAP];                    // ELL source lists

// ---------------- packed f32x2 / misc helpers ----------------
__device__ __forceinline__ unsigned long long ffma2(
    unsigned long long a, unsigned long long b, unsigned long long c) {
    unsigned long long d;
    asm("fma.rn.f32x2 %0, %1, %2, %3;" : "=l"(d) : "l"(a), "l"(b), "l"(c));
    return d;
}
__device__ __forceinline__ float unpack_add(unsigned long long v) {
    float lo, hi;
    asm("mov.b64 {%0, %1}, %2;" : "=f"(lo), "=f"(hi) : "l"(v));
    return lo + hi;
}
__device__ __forceinline__ float ex2f(float x) {
    float y;
    asm("ex2.approx.f32 %0, %1;" : "=f"(y) : "f"(x));
    return y;
}

// ---------------------------------------------------------------------------
// K0: zero degree counters (side stream, parallel with k1)
// ---------------------------------------------------------------------------
__global__ void k_zero() {
    int i = blockIdx.x * blockDim.x + threadIdx.x;
    if (i * 4 < N_NODES) *(int4*)&g_cnt[i * 4] = make_int4(0, 0, 0, 0);
}

// ---------------------------------------------------------------------------
// K1: x = relu(X @ W1^T + b1); xn = x/||x||; store xn (fp32 + half2) + nrm.
// 16 nodes/block, register-resident weights (f32x2), broadcast LDS.128.
// (R7/R12-proven — best SIMT k1; both constant-mem and MMA variants lost.)
// ---------------------------------------------------------------------------
__global__ void __launch_bounds__(256) k1_lin1_norm(
    const float* __restrict__ X,
    const float* __restrict__ W1,
    const float* __restrict__ b1)
{
    __shared__ float4 sX4[NB * NCHUNK];
    __shared__ float  psum[NB * 8 * 33];

    const int tid  = threadIdx.x;
    const int w    = tid >> 5;
    const int lane = tid & 31;

    const int base = (w < 7) ? 3 * w : 21;
    const int nch  = (w < 7) ? 3 : 4;

    const ulonglong2* W2v = (const ulonglong2*)W1;
    unsigned long long wlo[4], whi[4];
    #pragma unroll
    for (int j = 0; j < 4; j++) {
        if (j < nch) {
            ulonglong2 v = W2v[lane * NCHUNK + base + j];
            wlo[j] = v.x; whi[j] = v.y;
        } else { wlo[j] = 0ull; whi[j] = 0ull; }
    }

    const int node0 = blockIdx.x * NB;         // 100000 = 6250*16 exact
    const float4* X4 = (const float4*)X;
    for (int i = tid; i < NB * NCHUNK; i += 256) {
        int n = i / NCHUNK, c = i % NCHUNK;
        sX4[i] = X4[(size_t)(node0 + n) * NCHUNK + c];
    }
    __syncthreads();

    const ulonglong2* sX2v = (const ulonglong2*)sX4;
    #pragma unroll
    for (int n = 0; n < NB; n++) {
        unsigned long long a0 = 0ull, a1 = 0ull;
        #pragma unroll
        for (int j = 0; j < 4; j++) {
            if (j < nch) {
                ulonglong2 x = sX2v[n * NCHUNK + base + j];  // broadcast LDS.128
                a0 = ffma2(x.x, wlo[j], a0);
                a1 = ffma2(x.y, whi[j], a1);
            }
        }
        psum[(n * 8 + w) * 33 + lane] = unpack_add(a0) + unpack_add(a1);
    }
    __syncthreads();

    // warp w finalizes nodes w and w+8 (lane = hid)
    #pragma unroll
    for (int rep = 0; rep < 2; rep++) {
        const int n = w + rep * 8;
        float v = b1[lane];
        #pragma unroll
        for (int ww = 0; ww < 8; ww++)
            v += psum[(n * 8 + ww) * 33 + lane];
        v = fmaxf(v, 0.0f);

        float s = v * v;
        #pragma unroll
        for (int o = 16; o > 0; o >>= 1) s += __shfl_xor_sync(0xffffffffu, s, o);
        float nrm = fmaxf(sqrtf(s), 1e-12f);

        const int node = node0 + n;
        const float xnv = v / nrm;
        g_xnf[node * HID + lane] = xnv;

        float hi = __shfl_down_sync(0xffffffffu, xnv, 1);
        if ((lane & 1) == 0) {
            __half2 p = __floats2half2_rn(xnv, hi);
            g_xnh[node * 16 + (lane >> 1)] = *(unsigned*)&p;
        }
        if (lane == 0) g_nrm[node] = nrm;
    }
}

// ---------------------------------------------------------------------------
// ELL build: 4 edges per thread, int4 reads, 4 independent atomic chains.
// ---------------------------------------------------------------------------
__global__ void k_ell(const int* __restrict__ esrc,
                      const int* __restrict__ etgt) {
    int e0 = (blockIdx.x * blockDim.x + threadIdx.x) * 4;
    if (e0 >= N_EDGES) return;
    int4 s = *(const int4*)&esrc[e0];
    int4 t = *(const int4*)&etgt[e0];
    int p0 = atomicAdd(&g_cnt[t.x], 1);
    int p1 = atomicAdd(&g_cnt[t.y], 1);
    int p2 = atomicAdd(&g_cnt[t.z], 1);
    int p3 = atomicAdd(&g_cnt[t.w], 1);
    if (p0 < ELL_CAP) g_col[t.x * ELL_CAP + p0] = s.x;
    if (p1 < ELL_CAP) g_col[t.y * ELL_CAP + p1] = s.y;
    if (p2 < ELL_CAP) g_col[t.z * ELL_CAP + p2] = s.z;
    if (p3 < ELL_CAP) g_col[t.w * ELL_CAP + p3] = s.w;
}

// ---------------------------------------------------------------------------
// K_AGG: 8-lane group owns one node (4 nodes/warp); fp16 gathers; 4-way MLP.
// R12 structure + beta*log2e pre-scale (bare ex2/edge) + occupancy bound
// (regs capped for 5 CTAs/SM -> 40 warps, up from 4 CTAs/32 warps).
// ---------------------------------------------------------------------------
__device__ __forceinline__ void edge4(
    int cb, int jj, int deg, int cidx, unsigned gmask, int n, int sub,
    const float4 xts, float4& acc, float& den)
{
    const bool v0 = (cb + jj     < deg);
    const bool v1 = (cb + jj + 1 < deg);
    const bool v2 = (cb + jj + 2 < deg);
    const bool v3 = (cb + jj + 3 < deg);
    int s0 = __shfl_sync(gmask, cidx, jj,     8);
    int s1 = __shfl_sync(gmask, cidx, jj + 1, 8);
    int s2 = __shfl_sync(gmask, cidx, jj + 2, 8);
    int s3 = __shfl_sync(gmask, cidx, jj + 3, 8);
    s0 = v0 ? s0 : n;  s1 = v1 ? s1 : n;
    s2 = v2 ? s2 : n;  s3 = v3 ? s3 : n;

    const uint2 u0 = *(const uint2*)&g_xnh[s0 * 16 + sub * 2];
    const uint2 u1 = *(const uint2*)&g_xnh[s1 * 16 + sub * 2];
    const uint2 u2 = *(const uint2*)&g_xnh[s2 * 16 + sub * 2];
    const uint2 u3 = *(const uint2*)&g_xnh[s3 * 16 + sub * 2];
    const float r0 = g_nrm[s0], r1 = g_nrm[s1];
    const float r2 = g_nrm[s2], r3 = g_nrm[s3];

    float2 a0 = __half22float2(*(const __half2*)&u0.x);
    float2 b0 = __half22float2(*(const __half2*)&u0.y);
    float2 a1 = __half22float2(*(const __half2*)&u1.x);
    float2 b1 = __half22float2(*(const __half2*)&u1.y);
    float2 a2 = __half22float2(*(const __half2*)&u2.x);
    float2 b2 = __half22float2(*(const __half2*)&u2.y);
    float2 a3 = __half22float2(*(const __half2*)&u3.x);
    float2 b3 = __half22float2(*(const __half2*)&u3.y);

    // dot against pre-scaled target (beta*log2e folded)
    float d0 = a0.x*xts.x + a0.y*xts.y + b0.x*xts.z + b0.y*xts.w;
    float d1 = a1.x*xts.x + a1.y*xts.y + b1.x*xts.z + b1.y*xts.w;
    float d2 = a2.x*xts.x + a2.y*xts.y + b2.x*xts.z + b2.y*xts.w;
    float d3 = a3.x*xts.x + a3.y*xts.y + b3.x*xts.z + b3.y*xts.w;
    #pragma unroll
    for (int o = 4; o > 0; o >>= 1) {
        d0 += __shfl_xor_sync(gmask, d0, o);
        d1 += __shfl_xor_sync(gmask, d1, o);
        d2 += __shfl_xor_sync(gmask, d2, o);
        d3 += __shfl_xor_sync(gmask, d3, o);
    }
    const float w0 = v0 ? ex2f(d0) : 0.0f;
    const float w1 = v1 ? ex2f(d1) : 0.0f;
    const float w2 = v2 ? ex2f(d2) : 0.0f;
    const float w3 = v3 ? ex2f(d3) : 0.0f;
    const float c0 = w0 * r0, c1 = w1 * r1, c2 = w2 * r2, c3 = w3 * r3;
    acc.x = fmaf(c0, a0.x, fmaf(c1, a1.x, fmaf(c2, a2.x, fmaf(c3, a3.x, acc.x))));
    acc.y = fmaf(c0, a0.y, fmaf(c1, a1.y, fmaf(c2, a2.y, fmaf(c3, a3.y, acc.y))));
    acc.z = fmaf(c0, b0.x, fmaf(c1, b1.x, fmaf(c2, b2.x, fmaf(c3, b3.x, acc.z))));
    acc.w = fmaf(c0, b0.y, fmaf(c1, b1.y, fmaf(c2, b2.y, fmaf(c3, b3.y, acc.w))));
    den += (w0 + w1) + (w2 + w3);
}

__global__ void __launch_bounds__(256, 5) k_agg(
    const float* __restrict__ W2,
    const float* __restrict__ b2,
    const float* __restrict__ beta_p,
    float* __restrict__ out)
{
    const int tid  = threadIdx.x;
    const int lane = tid & 31;
    const int g    = lane >> 3;
    const int sub  = lane & 7;
    const unsigned gmask = 0xFFu << (g * 8);
    const int n = blockIdx.x * 32 + (tid >> 5) * 4 + g;   // 100000 = 3125*32

    const float S = (*beta_p) * 1.44269504088896f;        // beta * log2(e)
    const float4 xt = *(const float4*)&g_xnf[n * HID + sub * 4];
    const float4 xts = make_float4(xt.x * S, xt.y * S, xt.z * S, xt.w * S);
    const float nrm_n = g_nrm[n];
    int deg = g_cnt[n];
    if (deg > ELL_CAP) deg = ELL_CAP;
    const int* __restrict__ cols = &g_col[n * ELL_CAP];

    // self-loop: d = S * |xn|^2
    float d = xts.x*xt.x + xts.y*xt.y + xts.z*xt.z + xts.w*xt.w;
    #pragma unroll
    for (int o = 4; o > 0; o >>= 1) d += __shfl_xor_sync(gmask, d, o);
    float wl = ex2f(d);
    float cl = wl * nrm_n;
    float4 acc = make_float4(cl * xt.x, cl * xt.y, cl * xt.z, cl * xt.w);
    float  den = wl;

    for (int cb = 0; cb < deg; cb += 8) {
        const int cidx = cols[cb + sub];
        edge4(cb, 0, deg, cidx, gmask, n, sub, xts, acc, den);
        edge4(cb, 4, deg, cidx, gmask, n, sub, xts, acc, den);
    }

    const float inv = 1.0f / den;
    const float4 o4 = make_float4(acc.x * inv, acc.y * inv, acc.z * inv, acc.w * inv);

    const float4 w2a = *(const float4*)&W2[sub * 4];
    const float4 w2b = *(const float4*)&W2[HID + sub * 4];
    float p0 = o4.x * w2a.x + o4.y * w2a.y + o4.z * w2a.z + o4.w * w2a.w;
    float p1 = o4.x * w2b.x + o4.y * w2b.y + o4.z * w2b.z + o4.w * w2b.w;
    #pragma unroll
    for (int o = 4; o > 0; o >>= 1) {
        p0 += __shfl_xor_sync(gmask, p0, o);
        p1 += __shfl_xor_sync(gmask, p1, o);
    }

    if (sub == 0) {
        float l0 = p0 + b2[0];
        float l1 = p1 + b2[1];
        float m  = fmaxf(l0, l1);
        float z  = m + logf(expf(l0 - m) + expf(l1 - m));
        *(float2*)&out[n * 2] = make_float2(l0 - z, l1 - z);
    }
}

// ---------------------------------------------------------------------------
// Launch: {k_zero -> k_ell} on side stream overlaps k1 on main stream.
// Inputs (metadata order):
//   0: X [N,100] f32   1: lin1_w [32,100] f32   2: lin1_b [32] f32
//   3: beta scalar f32 4: lin2_w [2,32]  f32   5: lin2_b [2] f32
//   6: edge_index [2,E] i32 (row 0 = src, row 1 = tgt)
// Output: [N,2] f32 log-probs
// ---------------------------------------------------------------------------
extern "C" void kernel_launch(void* const* d_in, const int* in_sizes, int n_in,
                              void* d_out, int out_size)
{
    const float* X    = (const float*)d_in[0];
    const float* W1   = (const float*)d_in[1];
    const float* b1   = (const float*)d_in[2];
    const float* beta = (const float*)d_in[3];
    const float* W2   = (const float*)d_in[4];
    const float* b2   = (const float*)d_in[5];
    const int*   ei   = (const int*)  d_in[6];
    const int* esrc = ei;
    const int* etgt = ei + N_EDGES;
    float* out = (float*)d_out;

    cudaStream_t s2;
    cudaStreamCreateWithFlags(&s2, cudaStreamNonBlocking);
    cudaEvent_t eFork, eJoin;
    cudaEventCreateWithFlags(&eFork, cudaEventDisableTiming);
    cudaEventCreateWithFlags(&eJoin, cudaEventDisableTiming);

    cudaEventRecord(eFork, 0);
    cudaStreamWaitEvent(s2, eFork, 0);

    // edge pipeline on s2 (independent of k1)
    k_zero<<<(N_NODES / 4 + 255) / 256, 256, 0, s2>>>();
    k_ell<<<(N_EDGES / 4 + 255) / 256, 256, 0, s2>>>(esrc, etgt);

    // node pipeline on main stream
    k1_lin1_norm<<<N_NODES / NB, 256>>>(X, W1, b1);

    cudaEventRecord(eJoin, s2);
    cudaStreamWaitEvent(0, eJoin, 0);

    k_agg<<<N_NODES / 32, 256>>>(W2, b2, beta, out);

    cudaEventDestroy(eFork);
    cudaEventDestroy(eJoin);
    cudaStreamDestroy(s2);
}

// round 17
// speedup vs baseline: 1.1486x; 1.0815x over previous
#include <cuda_runtime.h>
#include <cuda_fp16.h>
#include <cstdint>
#include <math.h>

#define N_NODES 100000
#define N_FEAT  100
#define HID     32
#define N_EDGES 1600000
#define NCHUNK  25          // N_FEAT/4 float4 chunks per W1 row
#define ELL_CAP 128         // max in-degree slot (Poisson(16): P(>128) ~ 0)
#define NB      16          // nodes per block in K1
#define ELL_GRID 296        // 2 CTAs/SM: limit co-residency contention vs k1

// Scratch (static device globals — no allocations allowed)
__device__ float g_xnf[N_NODES * HID];                        // fp32 normalized feats
__device__ __align__(16) unsigned g_xnh[N_NODES * 16];        // half2-packed rows (64B)
__device__ float g_nrm[N_NODES];                              // row norms
__device__ int   g_cnt[N_NODES];                              // in-degree counters
__device__ int   g_col[N_NODES * ELL_CAP];                    // ELL source lists

// ---------------- packed f32x2 / misc helpers ----------------
__device__ __forceinline__ unsigned long long ffma2(
    unsigned long long a, unsigned long long b, unsigned long long c) {
    unsigned long long d;
    asm("fma.rn.f32x2 %0, %1, %2, %3;" : "=l"(d) : "l"(a), "l"(b), "l"(c));
    return d;
}
__device__ __forceinline__ float unpack_add(unsigned long long v) {
    float lo, hi;
    asm("mov.b64 {%0, %1}, %2;" : "=f"(lo), "=f"(hi) : "l"(v));
    return lo + hi;
}
__device__ __forceinline__ float ex2f(float x) {
    float y;
    asm("ex2.approx.f32 %0, %1;" : "=f"(y) : "f"(x));
    return y;
}

// ---------------------------------------------------------------------------
// K0: zero degree counters (side stream, parallel with k1)
// ---------------------------------------------------------------------------
__global__ void k_zero() {
    int i = blockIdx.x * blockDim.x + threadIdx.x;
    if (i * 4 < N_NODES) *(int4*)&g_cnt[i * 4] = make_int4(0, 0, 0, 0);
}

// ---------------------------------------------------------------------------
// K1: x = relu(X @ W1^T + b1); xn = x/||x||; store xn (fp32 + half2) + nrm.
// 16 nodes/block, register-resident weights (f32x2), broadcast LDS.128.
// (R7/R12-proven — unchanged.)
// ---------------------------------------------------------------------------
__global__ void __launch_bounds__(256) k1_lin1_norm(
    const float* __restrict__ X,
    const float* __restrict__ W1,
    const float* __restrict__ b1)
{
    __shared__ float4 sX4[NB * NCHUNK];
    __shared__ float  psum[NB * 8 * 33];

    const int tid  = threadIdx.x;
    const int w    = tid >> 5;
    const int lane = tid & 31;

    const int base = (w < 7) ? 3 * w : 21;
    const int nch  = (w < 7) ? 3 : 4;

    const ulonglong2* W2v = (const ulonglong2*)W1;
    unsigned long long wlo[4], whi[4];
    #pragma unroll
    for (int j = 0; j < 4; j++) {
        if (j < nch) {
            ulonglong2 v = W2v[lane * NCHUNK + base + j];
            wlo[j] = v.x; whi[j] = v.y;
        } else { wlo[j] = 0ull; whi[j] = 0ull; }
    }

    const int node0 = blockIdx.x * NB;         // 100000 = 6250*16 exact
    const float4* X4 = (const float4*)X;
    for (int i = tid; i < NB * NCHUNK; i += 256) {
        int n = i / NCHUNK, c = i % NCHUNK;
        sX4[i] = X4[(size_t)(node0 + n) * NCHUNK + c];
    }
    __syncthreads();

    const ulonglong2* sX2v = (const ulonglong2*)sX4;
    #pragma unroll
    for (int n = 0; n < NB; n++) {
        unsigned long long a0 = 0ull, a1 = 0ull;
        #pragma unroll
        for (int j = 0; j < 4; j++) {
            if (j < nch) {
                ulonglong2 x = sX2v[n * NCHUNK + base + j];  // broadcast LDS.128
                a0 = ffma2(x.x, wlo[j], a0);
                a1 = ffma2(x.y, whi[j], a1);
            }
        }
        psum[(n * 8 + w) * 33 + lane] = unpack_add(a0) + unpack_add(a1);
    }
    __syncthreads();

    // warp w finalizes nodes w and w+8 (lane = hid)
    #pragma unroll
    for (int rep = 0; rep < 2; rep++) {
        const int n = w + rep * 8;
        float v = b1[lane];
        #pragma unroll
        for (int ww = 0; ww < 8; ww++)
            v += psum[(n * 8 + ww) * 33 + lane];
        v = fmaxf(v, 0.0f);

        float s = v * v;
        #pragma unroll
        for (int o = 16; o > 0; o >>= 1) s += __shfl_xor_sync(0xffffffffu, s, o);
        float nrm = fmaxf(sqrtf(s), 1e-12f);

        const int node = node0 + n;
        const float xnv = v / nrm;
        g_xnf[node * HID + lane] = xnv;

        float hi = __shfl_down_sync(0xffffffffu, xnv, 1);
        if ((lane & 1) == 0) {
            __half2 p = __floats2half2_rn(xnv, hi);
            g_xnh[node * 16 + (lane >> 1)] = *(unsigned*)&p;
        }
        if (lane == 0) g_nrm[node] = nrm;
    }
}

// ---------------------------------------------------------------------------
// ELL build: grid-stride at 2 CTAs/SM (leaves SMs for k1 during overlap).
// 4 edges per iteration per thread, int4 reads, independent atomic chains.
// ---------------------------------------------------------------------------
__global__ void __launch_bounds__(256) k_ell(const int* __restrict__ esrc,
                                             const int* __restrict__ etgt) {
    const int stride = gridDim.x * blockDim.x * 4;
    for (int e0 = (blockIdx.x * blockDim.x + threadIdx.x) * 4;
         e0 < N_EDGES; e0 += stride) {
        int4 s = *(const int4*)&esrc[e0];
        int4 t = *(const int4*)&etgt[e0];
        int p0 = atomicAdd(&g_cnt[t.x], 1);
        int p1 = atomicAdd(&g_cnt[t.y], 1);
        int p2 = atomicAdd(&g_cnt[t.z], 1);
        int p3 = atomicAdd(&g_cnt[t.w], 1);
        if (p0 < ELL_CAP) g_col[t.x * ELL_CAP + p0] = s.x;
        if (p1 < ELL_CAP) g_col[t.y * ELL_CAP + p1] = s.y;
        if (p2 < ELL_CAP) g_col[t.z * ELL_CAP + p2] = s.z;
        if (p3 < ELL_CAP) g_col[t.w * ELL_CAP + p3] = s.w;
    }
}

// ---------------------------------------------------------------------------
// K_AGG: 8-lane group owns one node (4 nodes/warp); fp16 gathers; 4-way MLP.
// R12 structure (NO occupancy cap) + beta*log2e pre-scale -> bare ex2/edge.
// ---------------------------------------------------------------------------
__device__ __forceinline__ void edge4(
    int cb, int jj, int deg, int cidx, unsigned gmask, int n, int sub,
    const float4 xts, float4& acc, float& den)
{
    const bool v0 = (cb + jj     < deg);
    const bool v1 = (cb + jj + 1 < deg);
    const bool v2 = (cb + jj + 2 < deg);
    const bool v3 = (cb + jj + 3 < deg);
    int s0 = __shfl_sync(gmask, cidx, jj,     8);
    int s1 = __shfl_sync(gmask, cidx, jj + 1, 8);
    int s2 = __shfl_sync(gmask, cidx, jj + 2, 8);
    int s3 = __shfl_sync(gmask, cidx, jj + 3, 8);
    s0 = v0 ? s0 : n;  s1 = v1 ? s1 : n;
    s2 = v2 ? s2 : n;  s3 = v3 ? s3 : n;

    const uint2 u0 = *(const uint2*)&g_xnh[s0 * 16 + sub * 2];
    const uint2 u1 = *(const uint2*)&g_xnh[s1 * 16 + sub * 2];
    const uint2 u2 = *(const uint2*)&g_xnh[s2 * 16 + sub * 2];
    const uint2 u3 = *(const uint2*)&g_xnh[s3 * 16 + sub * 2];
    const float r0 = g_nrm[s0], r1 = g_nrm[s1];
    const float r2 = g_nrm[s2], r3 = g_nrm[s3];

    float2 a0 = __half22float2(*(const __half2*)&u0.x);
    float2 b0 = __half22float2(*(const __half2*)&u0.y);
    float2 a1 = __half22float2(*(const __half2*)&u1.x);
    float2 b1 = __half22float2(*(const __half2*)&u1.y);
    float2 a2 = __half22float2(*(const __half2*)&u2.x);
    float2 b2 = __half22float2(*(const __half2*)&u2.y);
    float2 a3 = __half22float2(*(const __half2*)&u3.x);
    float2 b3 = __half22float2(*(const __half2*)&u3.y);

    float d0 = a0.x*xts.x + a0.y*xts.y + b0.x*xts.z + b0.y*xts.w;
    float d1 = a1.x*xts.x + a1.y*xts.y + b1.x*xts.z + b1.y*xts.w;
    float d2 = a2.x*xts.x + a2.y*xts.y + b2.x*xts.z + b2.y*xts.w;
    float d3 = a3.x*xts.x + a3.y*xts.y + b3.x*xts.z + b3.y*xts.w;
    #pragma unroll
    for (int o = 4; o > 0; o >>= 1) {
        d0 += __shfl_xor_sync(gmask, d0, o);
        d1 += __shfl_xor_sync(gmask, d1, o);
        d2 += __shfl_xor_sync(gmask, d2, o);
        d3 += __shfl_xor_sync(gmask, d3, o);
    }
    const float w0 = v0 ? ex2f(d0) : 0.0f;
    const float w1 = v1 ? ex2f(d1) : 0.0f;
    const float w2 = v2 ? ex2f(d2) : 0.0f;
    const float w3 = v3 ? ex2f(d3) : 0.0f;
    const float c0 = w0 * r0, c1 = w1 * r1, c2 = w2 * r2, c3 = w3 * r3;
    acc.x = fmaf(c0, a0.x, fmaf(c1, a1.x, fmaf(c2, a2.x, fmaf(c3, a3.x, acc.x))));
    acc.y = fmaf(c0, a0.y, fmaf(c1, a1.y, fmaf(c2, a2.y, fmaf(c3, a3.y, acc.y))));
    acc.z = fmaf(c0, b0.x, fmaf(c1, b1.x, fmaf(c2, b2.x, fmaf(c3, b3.x, acc.z))));
    acc.w = fmaf(c0, b0.y, fmaf(c1, b1.y, fmaf(c2, b2.y, fmaf(c3, b3.y, acc.w))));
    den += (w0 + w1) + (w2 + w3);
}

__global__ void __launch_bounds__(256) k_agg(
    const float* __restrict__ W2,
    const float* __restrict__ b2,
    const float* __restrict__ beta_p,
    float* __restrict__ out)
{
    const int tid  = threadIdx.x;
    const int lane = tid & 31;
    const int g    = lane >> 3;
    const int sub  = lane & 7;
    const unsigned gmask = 0xFFu << (g * 8);
    const int n = blockIdx.x * 32 + (tid >> 5) * 4 + g;   // 100000 = 3125*32

    const float S = (*beta_p) * 1.44269504088896f;        // beta * log2(e)
    const float4 xt = *(const float4*)&g_xnf[n * HID + sub * 4];
    const float4 xts = make_float4(xt.x * S, xt.y * S, xt.z * S, xt.w * S);
    const float nrm_n = g_nrm[n];
    int deg = g_cnt[n];
    if (deg > ELL_CAP) deg = ELL_CAP;
    const int* __restrict__ cols = &g_col[n * ELL_CAP];

    // self-loop: d = S * |xn|^2
    float d = xts.x*xt.x + xts.y*xt.y + xts.z*xt.z + xts.w*xt.w;
    #pragma unroll
    for (int o = 4; o > 0; o >>= 1) d += __shfl_xor_sync(gmask, d, o);
    float wl = ex2f(d);
    float cl = wl * nrm_n;
    float4 acc = make_float4(cl * xt.x, cl * xt.y, cl * xt.z, cl * xt.w);
    float  den = wl;

    for (int cb = 0; cb < deg; cb += 8) {
        const int cidx = cols[cb + sub];
        edge4(cb, 0, deg, cidx, gmask, n, sub, xts, acc, den);
        edge4(cb, 4, deg, cidx, gmask, n, sub, xts, acc, den);
    }

    const float inv = 1.0f / den;
    const float4 o4 = make_float4(acc.x * inv, acc.y * inv, acc.z * inv, acc.w * inv);

    const float4 w2a = *(const float4*)&W2[sub * 4];
    const float4 w2b = *(const float4*)&W2[HID + sub * 4];
    float p0 = o4.x * w2a.x + o4.y * w2a.y + o4.z * w2a.z + o4.w * w2a.w;
    float p1 = o4.x * w2b.x + o4.y * w2b.y + o4.z * w2b.z + o4.w * w2b.w;
    #pragma unroll
    for (int o = 4; o > 0; o >>= 1) {
        p0 += __shfl_xor_sync(gmask, p0, o);
        p1 += __shfl_xor_sync(gmask, p1, o);
    }

    if (sub == 0) {
        float l0 = p0 + b2[0];
        float l1 = p1 + b2[1];
        float m  = fmaxf(l0, l1);
        float z  = m + logf(expf(l0 - m) + expf(l1 - m));
        *(float2*)&out[n * 2] = make_float2(l0 - z, l1 - z);
    }
}

// ---------------------------------------------------------------------------
// Launch: {k_zero -> k_ell(2 CTA/SM)} on side stream overlaps k1 on main.
// Inputs (metadata order):
//   0: X [N,100] f32   1: lin1_w [32,100] f32   2: lin1_b [32] f32
//   3: beta scalar f32 4: lin2_w [2,32]  f32   5: lin2_b [2] f32
//   6: edge_index [2,E] i32 (row 0 = src, row 1 = tgt)
// Output: [N,2] f32 log-probs
// ---------------------------------------------------------------------------
extern "C" void kernel_launch(void* const* d_in, const int* in_sizes, int n_in,
                              void* d_out, int out_size)
{
    const float* X    = (const float*)d_in[0];
    const float* W1   = (const float*)d_in[1];
    const float* b1   = (const float*)d_in[2];
    const float* beta = (const float*)d_in[3];
    const float* W2   = (const float*)d_in[4];
    const float* b2   = (const float*)d_in[5];
    const int*   ei   = (const int*)  d_in[6];
    const int* esrc = ei;
    const int* etgt = ei + N_EDGES;
    float* out = (float*)d_out;

    cudaStream_t s2;
    cudaStreamCreateWithFlags(&s2, cudaStreamNonBlocking);
    cudaEvent_t eFork, eJoin;
    cudaEventCreateWithFlags(&eFork, cudaEventDisableTiming);
    cudaEventCreateWithFlags(&eJoin, cudaEventDisableTiming);

    cudaEventRecord(eFork, 0);
    cudaStreamWaitEvent(s2, eFork, 0);

    // edge pipeline on s2, capped at 2 CTAs/SM
    k_zero<<<(N_NODES / 4 + 255) / 256, 256, 0, s2>>>();
    k_ell<<<ELL_GRID, 256, 0, s2>>>(esrc, etgt);

    // node pipeline on main stream
    k1_lin1_norm<<<N_NODES / NB, 256>>>(X, W1, b1);

    cudaEventRecord(eJoin, s2);
    cudaStreamWaitEvent(0, eJoin, 0);

    k_agg<<<N_NODES / 32, 256>>>(W2, b2, beta, out);

    cudaEventDestroy(eFork);
    cudaEventDestroy(eJoin);
    cudaStreamDestroy(s2);
}